// round 10
// baseline (speedup 1.0000x reference)
#include <cuda_runtime.h>
#include <cuda_bf16.h>
#include <math.h>

// ---------------------------------------------------------------------------
// GraphSAGE fraud detector (R10): aggregate fused into the tf32 MMA GEMM
// (one kernel per layer, gather writes tf32 straight to the A smem tile).
// Launch order arranged so ncu (-s 5) profiles the fused layer-0 kernel.
// ---------------------------------------------------------------------------

#define MAXN 100000
#define MAXE 1600000
#define F 64

__device__ int   g_deg[MAXN];
__device__ int   g_rowstart[MAXN];
__device__ int   g_cursor[MAXN];
__device__ int   g_srcs[MAXE];
__device__ float g_bufA[(size_t)MAXN * F];
__device__ float g_bufB[(size_t)MAXN * F];
__device__ float g_colsum[F];
__device__ int   g_bsum[256];

// ---------------------------------------------------------------------------
__global__ void init_kernel(int nNodes) {
    int i = blockIdx.x * blockDim.x + threadIdx.x;
    if (i < nNodes) g_deg[i] = 0;
    if (i < F) g_colsum[i] = 0.f;
}

__global__ void hist_kernel(const int* __restrict__ dst, int E) {
    int e = blockIdx.x * blockDim.x + threadIdx.x;
    if (e < E) atomicAdd(&g_deg[dst[e]], 1);
}

// --- 2-phase parallel exclusive scan over degrees (2 nodes / thread) -------
__global__ void scan_pass1(int nNodes) {
    int t = threadIdx.x, b = blockIdx.x;
    int base = (b * 256 + t) * 2;
    int s = 0;
    if (base < nNodes) s += g_deg[base];
    if (base + 1 < nNodes) s += g_deg[base + 1];
    __shared__ int sh[256];
    sh[t] = s;
    __syncthreads();
    for (int o = 128; o > 0; o >>= 1) {
        if (t < o) sh[t] += sh[t + o];
        __syncthreads();
    }
    if (t == 0) g_bsum[b] = sh[0];
}

// pass2 merged: every block redundantly scans the 256 block sums.
__global__ void scan_pass3(int nNodes) {
    __shared__ int sb[256];
    __shared__ int sh[256];
    int t = threadIdx.x, b = blockIdx.x;
    sb[t] = g_bsum[t];
    __syncthreads();
    for (int o = 1; o < 256; o <<= 1) {
        int u = (t >= o) ? sb[t - o] : 0;
        __syncthreads();
        sb[t] += u;
        __syncthreads();
    }
    int boff = (b > 0) ? sb[b - 1] : 0;

    int base = (b * 256 + t) * 2;
    int d0 = (base < nNodes) ? g_deg[base] : 0;
    int d1 = (base + 1 < nNodes) ? g_deg[base + 1] : 0;
    int s = d0 + d1;
    sh[t] = s;
    __syncthreads();
    for (int o = 1; o < 256; o <<= 1) {
        int u = (t >= o) ? sh[t - o] : 0;
        __syncthreads();
        sh[t] += u;
        __syncthreads();
    }
    int pre = boff + sh[t] - s;
    if (base < nNodes) { g_rowstart[base] = pre; g_cursor[base] = pre; }
    if (base + 1 < nNodes) { g_rowstart[base + 1] = pre + d0; g_cursor[base + 1] = pre + d0; }
}

__global__ void scatter_kernel(const int* __restrict__ src,
                               const int* __restrict__ dst, int E) {
    int e = blockIdx.x * blockDim.x + threadIdx.x;
    if (e < E) {
        int d = dst[e];
        int p = atomicAdd(&g_cursor[d], 1);
        g_srcs[p] = src[e];
    }
}

// ---------------------------------------------------------------------------
// Fused aggregate + dual GEMM (tf32 mma.sync m16n8k8).
// Block: 256 threads / 8 warps, tile M=64 rows.
//   Phase 1: each warp gathers+means 8 nodes (half-warp MLP-4 loop) and
//            writes [aggr | H] in tf32 straight into the A smem tile.
//   Phase 2: warps 0-3 run the MMA (M=16 each, N=64, K=128) and store.
#define AS_STRIDE 132
#define BS_STRIDE 72
#define AS_FLOATS (64 * AS_STRIDE)
#define BS_FLOATS (128 * BS_STRIDE)
#define GEMM_SMEM_BYTES ((AS_FLOATS + BS_FLOATS + 2 * F) * 4)

__device__ __forceinline__ float tf32f(float x) {
    unsigned int u;
    asm("cvt.rna.tf32.f32 %0, %1;" : "=r"(u) : "f"(x));
    return __uint_as_float(u);
}

__device__ __forceinline__ void mma_tf32(float* c, unsigned int a0,
                                         unsigned int a1, unsigned int a2,
                                         unsigned int a3, unsigned int b0,
                                         unsigned int b1) {
    asm("mma.sync.aligned.m16n8k8.row.col.f32.tf32.tf32.f32 "
        "{%0,%1,%2,%3}, {%4,%5,%6,%7}, {%8,%9}, {%0,%1,%2,%3};"
        : "+f"(c[0]), "+f"(c[1]), "+f"(c[2]), "+f"(c[3])
        : "r"(a0), "r"(a1), "r"(a2), "r"(a3), "r"(b0), "r"(b1));
}

template <bool BN_RELU>
__global__ void __launch_bounds__(256) fused_layer_kernel(
    const float* __restrict__ H,
    const float* __restrict__ wl, const float* __restrict__ wr,
    const float* __restrict__ bl,
    const float* __restrict__ gn, const float* __restrict__ be,
    const float* __restrict__ mn, const float* __restrict__ vr,
    float* __restrict__ out, int nNodes) {
    extern __shared__ float smem[];
    float* As = smem;                 // [64][AS_STRIDE]: [aggr|H] tf32
    float* Bs = smem + AS_FLOATS;     // [128][BS_STRIDE]: [Wl;Wr]^T tf32
    float* s_scale = Bs + BS_FLOATS;
    float* s_shift = s_scale + F;

    int tid = threadIdx.x;
    int warp = tid >> 5;
    int lane = tid & 31;
    int row0 = blockIdx.x * 64;

    // Stage weights transposed, tf32 (all 8 warps).
    const float4* wl4 = (const float4*)wl;
    const float4* wr4 = (const float4*)wr;
    for (int i = tid; i < 1024; i += 256) {
        int j = i >> 4;
        int kc = (i & 15) << 2;
        float4 a = __ldg(wl4 + i);
        Bs[(kc + 0) * BS_STRIDE + j] = tf32f(a.x);
        Bs[(kc + 1) * BS_STRIDE + j] = tf32f(a.y);
        Bs[(kc + 2) * BS_STRIDE + j] = tf32f(a.z);
        Bs[(kc + 3) * BS_STRIDE + j] = tf32f(a.w);
        float4 b = __ldg(wr4 + i);
        Bs[(64 + kc + 0) * BS_STRIDE + j] = tf32f(b.x);
        Bs[(64 + kc + 1) * BS_STRIDE + j] = tf32f(b.y);
        Bs[(64 + kc + 2) * BS_STRIDE + j] = tf32f(b.z);
        Bs[(64 + kc + 3) * BS_STRIDE + j] = tf32f(b.w);
    }
    if (BN_RELU && tid < F) {
        float sc = __ldg(&gn[tid]) * rsqrtf(__ldg(&vr[tid]) + 1e-5f);
        s_scale[tid] = sc;
        s_shift[tid] = (__ldg(&bl[tid]) - __ldg(&mn[tid])) * sc + __ldg(&be[tid]);
    }

    // Phase 1: warp w aggregates nodes row0 + 8w .. row0 + 8w + 7.
    int half = lane >> 4;
    int q = lane & 15;
    const float4* base4 = (const float4*)H;
#pragma unroll 1
    for (int nn = 0; nn < 8; ++nn) {
        int row = warp * 8 + nn;
        int grow = row0 + row;
        float* Arow = As + row * AS_STRIDE;
        if (grow < nNodes) {
            // Hoisted root-row load (half 1 will store it after the loop).
            float4 hv = __ldg(base4 + (size_t)grow * 16 + q);
            int start = g_rowstart[grow];
            int deg = g_deg[grow];
            float ax = 0.f, ay = 0.f, az = 0.f, aw = 0.f;
            int i = 0;
            for (; i + 8 <= deg; i += 8) {
                int b0 = start + i + 4 * half;
                int s0 = __ldg(&g_srcs[b0 + 0]);
                int s1 = __ldg(&g_srcs[b0 + 1]);
                int s2 = __ldg(&g_srcs[b0 + 2]);
                int s3 = __ldg(&g_srcs[b0 + 3]);
                float4 r0 = __ldg(base4 + s0 * 16 + q);
                float4 r1 = __ldg(base4 + s1 * 16 + q);
                float4 r2 = __ldg(base4 + s2 * 16 + q);
                float4 r3 = __ldg(base4 + s3 * 16 + q);
                ax += (r0.x + r1.x) + (r2.x + r3.x);
                ay += (r0.y + r1.y) + (r2.y + r3.y);
                az += (r0.z + r1.z) + (r2.z + r3.z);
                aw += (r0.w + r1.w) + (r2.w + r3.w);
            }
            for (; i < deg; i += 2) {
                int idx = i + half;
                if (idx < deg) {
                    int s = __ldg(&g_srcs[start + idx]);
                    float4 a = __ldg(base4 + s * 16 + q);
                    ax += a.x;
                    ay += a.y;
                    az += a.z;
                    aw += a.w;
                }
            }
            ax += __shfl_xor_sync(0xffffffffu, ax, 16);
            ay += __shfl_xor_sync(0xffffffffu, ay, 16);
            az += __shfl_xor_sync(0xffffffffu, az, 16);
            aw += __shfl_xor_sync(0xffffffffu, aw, 16);
            if (half == 0) {
                float inv = deg > 0 ? 1.0f / (float)deg : 0.f;
                float* dp = Arow + 4 * q;
                dp[0] = tf32f(ax * inv);
                dp[1] = tf32f(ay * inv);
                dp[2] = tf32f(az * inv);
                dp[3] = tf32f(aw * inv);
            } else {
                float* dp = Arow + 64 + 4 * q;
                dp[0] = tf32f(hv.x);
                dp[1] = tf32f(hv.y);
                dp[2] = tf32f(hv.z);
                dp[3] = tf32f(hv.w);
            }
        } else {
            // Zero-fill out-of-range rows (both halves cover 128 floats).
            float* dp = Arow + 64 * half + 4 * q;
            dp[0] = 0.f; dp[1] = 0.f; dp[2] = 0.f; dp[3] = 0.f;
        }
    }
    __syncthreads();

    // Phase 2: warps 0-3 run the MMA; warps 4-7 are done.
    if (warp >= 4) return;
    int qq = lane >> 2;
    int r = lane & 3;
    float c[8][4];
#pragma unroll
    for (int n = 0; n < 8; ++n)
#pragma unroll
        for (int t = 0; t < 4; ++t) c[n][t] = 0.f;

    int arow = warp * 16;
#pragma unroll 4
    for (int kt = 0; kt < 16; ++kt) {
        int k0 = kt * 8;
        const float* Ab = As + (arow + qq) * AS_STRIDE + k0 + r;
        unsigned int a0 = __float_as_uint(Ab[0]);
        unsigned int a1 = __float_as_uint(Ab[8 * AS_STRIDE]);
        unsigned int a2 = __float_as_uint(Ab[4]);
        unsigned int a3 = __float_as_uint(Ab[8 * AS_STRIDE + 4]);
#pragma unroll
        for (int n = 0; n < 8; ++n) {
            const float* Bb = Bs + (k0 + r) * BS_STRIDE + n * 8 + qq;
            unsigned int b0 = __float_as_uint(Bb[0]);
            unsigned int b1 = __float_as_uint(Bb[4 * BS_STRIDE]);
            mma_tf32(c[n], a0, a1, a2, a3, b0, b1);
        }
    }

    int gr0 = row0 + arow + qq;
    int gr1 = gr0 + 8;
#pragma unroll
    for (int n = 0; n < 8; ++n) {
        int j = n * 8 + 2 * r;
        float x0 = c[n][0], x1 = c[n][1], x2 = c[n][2], x3 = c[n][3];
        if (BN_RELU) {
            float sc0 = s_scale[j], sh0 = s_shift[j];
            float sc1 = s_scale[j + 1], sh1 = s_shift[j + 1];
            x0 = fmaxf(fmaf(x0, sc0, sh0), 0.f);
            x1 = fmaxf(fmaf(x1, sc1, sh1), 0.f);
            x2 = fmaxf(fmaf(x2, sc0, sh0), 0.f);
            x3 = fmaxf(fmaf(x3, sc1, sh1), 0.f);
        }
        if (gr0 < nNodes)
            *(float2*)(out + (size_t)gr0 * F + j) = make_float2(x0, x1);
        if (gr1 < nNodes)
            *(float2*)(out + (size_t)gr1 * F + j) = make_float2(x2, x3);
    }
}

// ---------------------------------------------------------------------------
__global__ void colsum_kernel(const float* __restrict__ hin, int nNodes) {
    int t = blockIdx.x * blockDim.x + threadIdx.x;
    int col = t & 63;
    int r = t >> 6;
    int stride = (gridDim.x * blockDim.x) >> 6;
    float s = 0.f;
    for (; r < nNodes; r += stride) s += __ldg(&hin[(size_t)r * F + col]);
    atomicAdd(&g_colsum[col], s);
}

__global__ void head_kernel(const float* __restrict__ bl2,
                            const float* __restrict__ cw1,
                            const float* __restrict__ cb1,
                            const float* __restrict__ cw2,
                            const float* __restrict__ cb2,
                            float* __restrict__ outp, int nNodes) {
    __shared__ float mean[F];
    __shared__ float z[F];
    int t = threadIdx.x;
    mean[t] = g_colsum[t] / (float)nNodes + __ldg(&bl2[t]);
    __syncthreads();
    float s = __ldg(&cb1[t]);
#pragma unroll
    for (int j = 0; j < F; ++j) s = fmaf(mean[j], __ldg(&cw1[t * F + j]), s);
    z[t] = fmaxf(s, 0.f);
    __syncthreads();
    if (t == 0) {
        float o = __ldg(&cb2[0]);
#pragma unroll
        for (int i = 0; i < F; ++i) o = fmaf(z[i], __ldg(&cw2[i]), o);
        outp[0] = 1.f / (1.f + expf(-o));
    }
}

// ---------------------------------------------------------------------------
extern "C" void kernel_launch(void* const* d_in, const int* in_sizes, int n_in,
                              void* d_out, int out_size) {
    const float* x    = (const float*)d_in[0];
    const int*   eidx = (const int*)d_in[1];
    const float* w_l0 = (const float*)d_in[2];
    const float* b_l0 = (const float*)d_in[3];
    const float* w_r0 = (const float*)d_in[4];
    const float* w_l1 = (const float*)d_in[5];
    const float* b_l1 = (const float*)d_in[6];
    const float* w_r1 = (const float*)d_in[7];
    const float* w_l2 = (const float*)d_in[8];
    const float* b_l2 = (const float*)d_in[9];
    const float* w_r2 = (const float*)d_in[10];
    const float* g0   = (const float*)d_in[11];
    const float* be0  = (const float*)d_in[12];
    const float* m0   = (const float*)d_in[13];
    const float* v0   = (const float*)d_in[14];
    const float* g1   = (const float*)d_in[15];
    const float* be1  = (const float*)d_in[16];
    const float* m1   = (const float*)d_in[17];
    const float* v1   = (const float*)d_in[18];
    const float* cw1  = (const float*)d_in[19];
    const float* cb1  = (const float*)d_in[20];
    const float* cw2  = (const float*)d_in[21];
    const float* cb2  = (const float*)d_in[22];
    float* out = (float*)d_out;

    int nN = in_sizes[0] / F;
    int E = in_sizes[1] / 2;
    if (nN > MAXN) nN = MAXN;
    if (E > MAXE) E = MAXE;
    const int* srcp = eidx;
    const int* dstp = eidx + E;

    float *bufA, *bufB;
    cudaGetSymbolAddress((void**)&bufA, g_bufA);
    cudaGetSymbolAddress((void**)&bufB, g_bufB);

    cudaFuncSetAttribute(fused_layer_kernel<true>,
                         cudaFuncAttributeMaxDynamicSharedMemorySize,
                         GEMM_SMEM_BYTES);
    cudaFuncSetAttribute(fused_layer_kernel<false>,
                         cudaFuncAttributeMaxDynamicSharedMemorySize,
                         GEMM_SMEM_BYTES);

    int tb = 256;
    int layerBlocks = (nN + 63) / 64;

    // Launch order fixed so ncu (-s 5 -c 1) profiles fused layer 0:
    // init(0), hist(1), scan1(2), scan3(3), scatter(4), fused<true>(5).
    init_kernel<<<(nN + tb - 1) / tb, tb>>>(nN);
    hist_kernel<<<(E + tb - 1) / tb, tb>>>(dstp, E);
    scan_pass1<<<256, 256>>>(nN);
    scan_pass3<<<256, 256>>>(nN);
    scatter_kernel<<<(E + tb - 1) / tb, tb>>>(srcp, dstp, E);

    // Layer 0: x -> bufA
    fused_layer_kernel<true><<<layerBlocks, 256, GEMM_SMEM_BYTES>>>(
        x, w_l0, w_r0, b_l0, g0, be0, m0, v0, bufA, nN);
    // Layer 1: bufA -> bufB
    fused_layer_kernel<true><<<layerBlocks, 256, GEMM_SMEM_BYTES>>>(
        bufA, w_l1, w_r1, b_l1, g1, be1, m1, v1, bufB, nN);
    // Layer 2: bufB -> bufA (no BN/ReLU, bias deferred)
    fused_layer_kernel<false><<<layerBlocks, 256, GEMM_SMEM_BYTES>>>(
        bufB, w_l2, w_r2, b_l2, nullptr, nullptr, nullptr, nullptr, bufA, nN);

    colsum_kernel<<<256, tb>>>(bufA, nN);
    head_kernel<<<1, F>>>(b_l2, cw1, cb1, cw2, cb2, out, nN);
}